// round 1
// baseline (speedup 1.0000x reference)
#include <cuda_runtime.h>
#include <math.h>

#define NLAYERS 12
#define DMODEL  256
#define DINNER  512
#define DTRANK  16
#define DSTATE  16
#define INDIM   230
#define BATCH   4096
#define ROWS    32
#define NTHREADS 512

// ---------------------------------------------------------------------------
// packed f32x2 FMA (Blackwell FFMA2): d = a*b + d on both lanes
// ---------------------------------------------------------------------------
union F2 { float2 f; unsigned long long u; };

__device__ __forceinline__ void ffma2(F2 &d, const F2 a, const F2 b) {
    asm("fma.rn.f32x2 %0, %1, %2, %0;" : "+l"(d.u) : "l"(a.u), "l"(b.u));
}

__device__ __forceinline__ float silu_f(float v) {
    return v * (1.0f / (1.0f + expf(-v)));
}
__device__ __forceinline__ float softplus_f(float v) {
    return (v > 20.0f) ? v : log1pf(expf(v));
}

// ---------------------------------------------------------------------------
// One block = 32 batch rows, runs the full 12-layer stack out of SMEM.
// SMEM: h[32][256], xz[32][1024], dbl[32][48], bc[32]   (~166 KB)
// ---------------------------------------------------------------------------
extern "C" __global__ void __launch_bounds__(NTHREADS, 1)
mamba_icl_kernel(const float* __restrict__ x,          // [4096,230]
                 const float* __restrict__ Wi,         // [230,256]
                 const float* __restrict__ bi,         // [256]
                 const float* __restrict__ in_proj_w,  // [12,256,1024]
                 const float* __restrict__ conv_w,     // [12,512,4]
                 const float* __restrict__ conv_b,     // [12,512]
                 const float* __restrict__ x_proj_w,   // [12,512,48]
                 const float* __restrict__ dt_proj_w,  // [12,16,512]
                 const float* __restrict__ dt_proj_b,  // [12,512]
                 const float* __restrict__ Dvec,       // [12,512]
                 const float* __restrict__ out_proj_w, // [12,512,256]
                 const float* __restrict__ Wo,         // [256,1]
                 const float* __restrict__ bo,         // [1]
                 float* __restrict__ out)              // [4096,1]
{
    extern __shared__ float sm[];
    float* sh_h   = sm;                         // 32*256  = 8192
    float* sh_xz  = sm + ROWS * DMODEL;         // 32*1024 = 32768
    float* sh_dbl = sh_xz + ROWS * 2 * DINNER;  // 32*48   = 1536
    float* sh_bc  = sh_dbl + ROWS * 48;         // 32

    const int t    = threadIdx.x;
    const int row0 = blockIdx.x * ROWS;
    const int tx   = t & 127;   // 128 groups along N
    const int ty   = t >> 7;    // 4 groups of 8 rows

    // =====================================================================
    // Input projection: h = x @ Wi + bi     [32,230] @ [230,256]
    // each thread: 8 rows x 2 cols (1 f32x2 pair)
    // =====================================================================
    {
        F2 acc[8];
        #pragma unroll
        for (int i = 0; i < 8; i++) acc[i].f = make_float2(0.f, 0.f);

        #pragma unroll 2
        for (int k = 0; k < INDIM; k++) {
            F2 w; w.f = *(const float2*)(Wi + k * DMODEL + tx * 2);
            #pragma unroll
            for (int i = 0; i < 8; i++) {
                float a = x[(size_t)(row0 + ty * 8 + i) * INDIM + k]; // warp-uniform
                F2 aa; aa.f = make_float2(a, a);
                ffma2(acc[i], aa, w);
            }
        }
        float2 bv = *(const float2*)(bi + tx * 2);
        #pragma unroll
        for (int i = 0; i < 8; i++) {
            sh_h[(ty * 8 + i) * DMODEL + tx * 2]     = acc[i].f.x + bv.x;
            sh_h[(ty * 8 + i) * DMODEL + tx * 2 + 1] = acc[i].f.y + bv.y;
        }
    }
    __syncthreads();

    // =====================================================================
    // 12 Mamba layers
    // =====================================================================
    for (int l = 0; l < NLAYERS; l++) {
        const float* Wp = in_proj_w  + (size_t)l * DMODEL * 2 * DINNER;
        const float* Cw = conv_w     + (size_t)l * DINNER * 4;
        const float* Cb = conv_b     + (size_t)l * DINNER;
        const float* Xp = x_proj_w   + (size_t)l * DINNER * 48;
        const float* Dw = dt_proj_w  + (size_t)l * DTRANK * DINNER;
        const float* Db = dt_proj_b  + (size_t)l * DINNER;
        const float* Dd = Dvec       + (size_t)l * DINNER;
        const float* Op = out_proj_w + (size_t)l * DINNER * DMODEL;

        // ---- GEMM1: xz = h @ in_proj   [32,256]@[256,1024] ----
        // each thread: 8 rows x 8 cols (4 f32x2 pairs)
        {
            F2 acc[8][4];
            #pragma unroll
            for (int i = 0; i < 8; i++)
                #pragma unroll
                for (int j = 0; j < 4; j++) acc[i][j].f = make_float2(0.f, 0.f);

            #pragma unroll 2
            for (int k = 0; k < DMODEL; k++) {
                const float4 w0 = *(const float4*)(Wp + (size_t)k * 1024 + tx * 8);
                const float4 w1 = *(const float4*)(Wp + (size_t)k * 1024 + tx * 8 + 4);
                F2 b0, b1, b2, b3;
                b0.f = make_float2(w0.x, w0.y);
                b1.f = make_float2(w0.z, w0.w);
                b2.f = make_float2(w1.x, w1.y);
                b3.f = make_float2(w1.z, w1.w);
                #pragma unroll
                for (int i = 0; i < 8; i++) {
                    float a = sh_h[(ty * 8 + i) * DMODEL + k];   // warp broadcast
                    F2 aa; aa.f = make_float2(a, a);
                    ffma2(acc[i][0], aa, b0);
                    ffma2(acc[i][1], aa, b1);
                    ffma2(acc[i][2], aa, b2);
                    ffma2(acc[i][3], aa, b3);
                }
            }
            #pragma unroll
            for (int i = 0; i < 8; i++)
                #pragma unroll
                for (int j = 0; j < 4; j++)
                    *(float2*)(sh_xz + (ty * 8 + i) * 1024 + tx * 8 + j * 2) = acc[i][j].f;
        }
        __syncthreads();

        // ---- conv(+bias)+silu: L=1 so only tap 3 of the conv is live ----
        #pragma unroll
        for (int p = 0; p < (ROWS * DINNER) / NTHREADS; p++) {
            int idx = t + p * NTHREADS;
            int r = idx >> 9, c = idx & 511;
            float v = sh_xz[r * 1024 + c] * Cw[c * 4 + 3] + Cb[c];
            sh_xz[r * 1024 + c] = silu_f(v);
        }
        __syncthreads();

        // ---- GEMM2: dbl = xc @ x_proj   [32,512]@[512,48] ----
        // 1536 outputs, 3 per thread
        {
            int o0 = t, o1 = t + 512, o2 = t + 1024;
            int r0 = o0 / 48, j0 = o0 - r0 * 48;
            int r1 = o1 / 48, j1 = o1 - r1 * 48;
            int r2 = o2 / 48, j2 = o2 - r2 * 48;
            float a0 = 0.f, a1 = 0.f, a2 = 0.f;
            #pragma unroll 4
            for (int k = 0; k < DINNER; k++) {
                const float* wr = Xp + (size_t)k * 48;
                a0 = fmaf(sh_xz[r0 * 1024 + k], wr[j0], a0);
                a1 = fmaf(sh_xz[r1 * 1024 + k], wr[j1], a1);
                a2 = fmaf(sh_xz[r2 * 1024 + k], wr[j2], a2);
            }
            sh_dbl[o0] = a0;
            sh_dbl[o1] = a1;
            sh_dbl[o2] = a2;
        }
        __syncthreads();

        // ---- bc[r] = dot(B, C) over D_STATE ----
        if (t < ROWS) {
            float s = 0.f;
            #pragma unroll
            for (int j = 0; j < DSTATE; j++)
                s = fmaf(sh_dbl[t * 48 + DTRANK + j], sh_dbl[t * 48 + DTRANK + DSTATE + j], s);
            sh_bc[t] = s;
        }
        __syncthreads();

        // ---- fused dt projection + softplus + gating:  y in place of xc ----
        #pragma unroll
        for (int p = 0; p < (ROWS * DINNER) / NTHREADS; p++) {
            int idx = t + p * NTHREADS;
            int r = idx >> 9, c = idx & 511;
            float sdt = Db[c];
            #pragma unroll
            for (int j = 0; j < DTRANK; j++)
                sdt = fmaf(sh_dbl[r * 48 + j], Dw[j * DINNER + c], sdt);
            float dt = softplus_f(sdt);
            float zv = sh_xz[r * 1024 + DINNER + c];
            float y  = sh_xz[r * 1024 + c] * (dt * sh_bc[r] + Dd[c]) * silu_f(zv);
            sh_xz[r * 1024 + c] = y;
        }
        __syncthreads();

        // ---- GEMM3: h = y @ out_proj   [32,512]@[512,256] ----
        // each thread: 8 rows x 2 cols (1 f32x2 pair)
        {
            F2 acc[8];
            #pragma unroll
            for (int i = 0; i < 8; i++) acc[i].f = make_float2(0.f, 0.f);

            #pragma unroll 4
            for (int k = 0; k < DINNER; k++) {
                F2 w; w.f = *(const float2*)(Op + (size_t)k * DMODEL + tx * 2);
                #pragma unroll
                for (int i = 0; i < 8; i++) {
                    float a = sh_xz[(ty * 8 + i) * 1024 + k];   // warp broadcast
                    F2 aa; aa.f = make_float2(a, a);
                    ffma2(acc[i], aa, w);
                }
            }
            #pragma unroll
            for (int i = 0; i < 8; i++)
                *(float2*)(sh_h + (ty * 8 + i) * DMODEL + tx * 2) = acc[i].f;
        }
        __syncthreads();
    }

    // =====================================================================
    // Output head: out = h @ Wo + bo
    // =====================================================================
    if (t < ROWS) {
        float s = 0.f;
        #pragma unroll 8
        for (int m = 0; m < DMODEL; m++)
            s = fmaf(sh_h[t * DMODEL + m], Wo[m], s);
        out[row0 + t] = s + bo[0];
    }
}

// ---------------------------------------------------------------------------
// launch
// ---------------------------------------------------------------------------
extern "C" void kernel_launch(void* const* d_in, const int* in_sizes, int n_in,
                              void* d_out, int out_size)
{
    (void)in_sizes; (void)n_in; (void)out_size;

    const size_t smem_bytes =
        (size_t)(ROWS * DMODEL + ROWS * 2 * DINNER + ROWS * 48 + ROWS) * sizeof(float);

    cudaFuncSetAttribute(mamba_icl_kernel,
                         cudaFuncAttributeMaxDynamicSharedMemorySize,
                         (int)smem_bytes);

    mamba_icl_kernel<<<BATCH / ROWS, NTHREADS, smem_bytes>>>(
        (const float*)d_in[0],   // x
        (const float*)d_in[1],   // Wi
        (const float*)d_in[2],   // bi
        (const float*)d_in[3],   // in_proj_w
        (const float*)d_in[4],   // conv_w
        (const float*)d_in[5],   // conv_b
        (const float*)d_in[6],   // x_proj_w
        (const float*)d_in[7],   // dt_proj_w
        (const float*)d_in[8],   // dt_proj_b
        // d_in[9] = A_log is mathematically dead (h0 = 0, L = 1)
        (const float*)d_in[10],  // D
        (const float*)d_in[11],  // out_proj_w
        (const float*)d_in[12],  // Wo
        (const float*)d_in[13],  // bo
        (float*)d_out);
}

// round 2
// speedup vs baseline: 1.1187x; 1.1187x over previous
#include <cuda_runtime.h>
#include <math.h>

#define NLAYERS 12
#define DMODEL  256
#define DINNER  512
#define DTRANK  16
#define DSTATE  16
#define INDIM   230
#define BATCH   4096
#define ROWS    16
#define NTHREADS 256

// ---------------------------------------------------------------------------
// packed f32x2 FMA (Blackwell FFMA2): d = a*b + d on both lanes
// ---------------------------------------------------------------------------
union F2 { float2 f; unsigned long long u; };

__device__ __forceinline__ void ffma2(F2 &d, const F2 a, const F2 b) {
    asm("fma.rn.f32x2 %0, %1, %2, %0;" : "+l"(d.u) : "l"(a.u), "l"(b.u));
}
__device__ __forceinline__ F2 bcast2(float v) { F2 r; r.f = make_float2(v, v); return r; }

__device__ __forceinline__ float silu_f(float v) {
    return v * (1.0f / (1.0f + __expf(-v)));
}
__device__ __forceinline__ float softplus_f(float v) {
    return (v > 20.0f) ? v : log1pf(__expf(v));
}

// ---------------------------------------------------------------------------
// One block = 16 batch rows; 2 CTAs/SM. Full 12-layer stack out of SMEM.
// SMEM: h[16][256], xz[16][1024], dbl[16][48], bc[16]  (~85 KB)
// ---------------------------------------------------------------------------
extern "C" __global__ void __launch_bounds__(NTHREADS, 2)
mamba_icl_kernel(const float* __restrict__ x,          // [4096,230]
                 const float* __restrict__ Wi,         // [230,256]
                 const float* __restrict__ bi,         // [256]
                 const float* __restrict__ in_proj_w,  // [12,256,1024]
                 const float* __restrict__ conv_w,     // [12,512,4]
                 const float* __restrict__ conv_b,     // [12,512]
                 const float* __restrict__ x_proj_w,   // [12,512,48]
                 const float* __restrict__ dt_proj_w,  // [12,16,512]
                 const float* __restrict__ dt_proj_b,  // [12,512]
                 const float* __restrict__ Dvec,       // [12,512]
                 const float* __restrict__ out_proj_w, // [12,512,256]
                 const float* __restrict__ Wo,         // [256,1]
                 const float* __restrict__ bo,         // [1]
                 float* __restrict__ out)              // [4096,1]
{
    extern __shared__ float sm[];
    float* sh_h   = sm;                         // 16*256  = 4096
    float* sh_xz  = sm + ROWS * DMODEL;         // 16*1024 = 16384
    float* sh_dbl = sh_xz + ROWS * 2 * DINNER;  // 16*48   = 768
    float* sh_bc  = sh_dbl + ROWS * 48;         // 16

    const int t    = threadIdx.x;
    const int row0 = blockIdx.x * ROWS;
    const int tx   = t & 127;   // 128 column groups
    const int ty   = t >> 7;    // 2 row groups of 8 rows

    // =====================================================================
    // Stage x rows into SMEM (coalesced), reuse sh_xz as scratch
    // =====================================================================
    float* sh_x = sh_xz;
    for (int idx = t; idx < ROWS * INDIM; idx += NTHREADS) {
        int r = idx / INDIM, c = idx - r * INDIM;
        sh_x[r * INDIM + c] = x[(size_t)(row0 + r) * INDIM + c];
    }
    __syncthreads();

    // =====================================================================
    // Input projection: h = x @ Wi + bi   [16,230]@[230,256]
    // thread: 8 rows x 2 cols
    // =====================================================================
    {
        F2 acc[8];
        #pragma unroll
        for (int i = 0; i < 8; i++) acc[i].f = make_float2(0.f, 0.f);

        const int rbase = ty * 8;
        #pragma unroll 2
        for (int k0 = 0; k0 < INDIM; k0 += 2) {
            F2 w0; w0.f = *(const float2*)(Wi + (size_t)k0 * DMODEL + tx * 2);
            F2 w1; w1.f = *(const float2*)(Wi + (size_t)(k0 + 1) * DMODEL + tx * 2);
            #pragma unroll
            for (int i = 0; i < 8; i++) {
                float2 a2 = *(const float2*)(sh_x + (rbase + i) * INDIM + k0);
                ffma2(acc[i], bcast2(a2.x), w0);
                ffma2(acc[i], bcast2(a2.y), w1);
            }
        }
        __syncthreads();   // done reading sh_x before anything overwrites sh_xz
        float2 bv = *(const float2*)(bi + tx * 2);
        #pragma unroll
        for (int i = 0; i < 8; i++) {
            sh_h[(rbase + i) * DMODEL + tx * 2]     = acc[i].f.x + bv.x;
            sh_h[(rbase + i) * DMODEL + tx * 2 + 1] = acc[i].f.y + bv.y;
        }
    }
    __syncthreads();

    // =====================================================================
    // 12 Mamba layers
    // =====================================================================
    for (int l = 0; l < NLAYERS; l++) {
        const float* Wp = in_proj_w  + (size_t)l * DMODEL * 2 * DINNER;
        const float* Cw = conv_w     + (size_t)l * DINNER * 4;
        const float* Cb = conv_b     + (size_t)l * DINNER;
        const float* Xp = x_proj_w   + (size_t)l * DINNER * 48;
        const float* Dw = dt_proj_w  + (size_t)l * DTRANK * DINNER;
        const float* Db = dt_proj_b  + (size_t)l * DINNER;
        const float* Dd = Dvec       + (size_t)l * DINNER;
        const float* Op = out_proj_w + (size_t)l * DINNER * DMODEL;

        // ---- GEMM1 + fused conv/silu epilogue:  [16,256]@[256,1024] ----
        // thread: 8 rows x 8 cols; k in chunks of 2
        {
            F2 acc[8][4];
            #pragma unroll
            for (int i = 0; i < 8; i++)
                #pragma unroll
                for (int j = 0; j < 4; j++) acc[i][j].f = make_float2(0.f, 0.f);

            const int rbase = ty * 8;
            #pragma unroll 2
            for (int k0 = 0; k0 < DMODEL; k0 += 2) {
                const float* wk = Wp + (size_t)k0 * 1024 + tx * 8;
                float4 w00 = *(const float4*)(wk);
                float4 w01 = *(const float4*)(wk + 4);
                float4 w10 = *(const float4*)(wk + 1024);
                float4 w11 = *(const float4*)(wk + 1028);
                F2 b00, b01, b02, b03, b10, b11, b12, b13;
                b00.f = make_float2(w00.x, w00.y); b01.f = make_float2(w00.z, w00.w);
                b02.f = make_float2(w01.x, w01.y); b03.f = make_float2(w01.z, w01.w);
                b10.f = make_float2(w10.x, w10.y); b11.f = make_float2(w10.z, w10.w);
                b12.f = make_float2(w11.x, w11.y); b13.f = make_float2(w11.z, w11.w);
                #pragma unroll
                for (int i = 0; i < 8; i++) {
                    float2 a2 = *(const float2*)(sh_h + (rbase + i) * DMODEL + k0);
                    F2 ax = bcast2(a2.x), ay = bcast2(a2.y);
                    ffma2(acc[i][0], ax, b00);
                    ffma2(acc[i][1], ax, b01);
                    ffma2(acc[i][2], ax, b02);
                    ffma2(acc[i][3], ax, b03);
                    ffma2(acc[i][0], ay, b10);
                    ffma2(acc[i][1], ay, b11);
                    ffma2(acc[i][2], ay, b12);
                    ffma2(acc[i][3], ay, b13);
                }
            }
            // epilogue: fused (conv tap3 + bias + silu) on xr half, silu on z half
            if (tx < 64) {
                #pragma unroll
                for (int j = 0; j < 4; j++) {
                    int c = tx * 8 + j * 2;
                    float cw0 = Cw[c * 4 + 3],       cb0 = Cb[c];
                    float cw1 = Cw[(c + 1) * 4 + 3], cb1 = Cb[c + 1];
                    #pragma unroll
                    for (int i = 0; i < 8; i++) {
                        float v0 = silu_f(acc[i][j].f.x * cw0 + cb0);
                        float v1 = silu_f(acc[i][j].f.y * cw1 + cb1);
                        *(float2*)(sh_xz + (rbase + i) * 1024 + c) = make_float2(v0, v1);
                    }
                }
            } else {
                #pragma unroll
                for (int j = 0; j < 4; j++) {
                    int c = tx * 8 + j * 2;
                    #pragma unroll
                    for (int i = 0; i < 8; i++) {
                        float v0 = silu_f(acc[i][j].f.x);
                        float v1 = silu_f(acc[i][j].f.y);
                        *(float2*)(sh_xz + (rbase + i) * 1024 + c) = make_float2(v0, v1);
                    }
                }
            }
        }
        __syncthreads();

        // ---- GEMM2: dbl = xc @ x_proj   [16,512]@[512,48]  (768 outputs) ----
        {
            int o0 = t, o1 = t + 256, o2 = t + 512;
            int r0 = o0 / 48, j0 = o0 - r0 * 48;
            int r1 = o1 / 48, j1 = o1 - r1 * 48;
            int r2 = o2 / 48, j2 = o2 - r2 * 48;
            float a0 = 0.f, a1 = 0.f, a2 = 0.f;
            #pragma unroll 8
            for (int k = 0; k < DINNER; k++) {
                const float* wr = Xp + (size_t)k * 48;
                a0 = fmaf(sh_xz[r0 * 1024 + k], wr[j0], a0);
                a1 = fmaf(sh_xz[r1 * 1024 + k], wr[j1], a1);
                a2 = fmaf(sh_xz[r2 * 1024 + k], wr[j2], a2);
            }
            sh_dbl[o0] = a0;
            sh_dbl[o1] = a1;
            sh_dbl[o2] = a2;
        }
        __syncthreads();

        // ---- bc[r] = dot(B, C) over D_STATE ----
        if (t < ROWS) {
            float s = 0.f;
            #pragma unroll
            for (int j = 0; j < DSTATE; j++)
                s = fmaf(sh_dbl[t * 48 + DTRANK + j], sh_dbl[t * 48 + DTRANK + DSTATE + j], s);
            sh_bc[t] = s;
        }
        __syncthreads();

        // ---- fused dt projection + softplus + gating (y in place of xc) ----
        // thread owns columns {2t, 2t+1}; dt weights hoisted to registers
        {
            const int c = t * 2;
            F2 dw[DTRANK];
            #pragma unroll
            for (int j = 0; j < DTRANK; j++)
                dw[j].f = *(const float2*)(Dw + j * DINNER + c);
            const float2 dbv = *(const float2*)(Db + c);
            const float2 ddv = *(const float2*)(Dd + c);

            #pragma unroll 2
            for (int r = 0; r < ROWS; r++) {
                F2 sdt; sdt.f = dbv;
                #pragma unroll
                for (int j = 0; j < DTRANK; j++)
                    ffma2(sdt, bcast2(sh_dbl[r * 48 + j]), dw[j]);
                float dt0 = softplus_f(sdt.f.x);
                float dt1 = softplus_f(sdt.f.y);
                float bcr = sh_bc[r];
                float2 xc = *(const float2*)(sh_xz + r * 1024 + c);
                float2 sz = *(const float2*)(sh_xz + r * 1024 + DINNER + c);  // already silu'd
                float y0 = xc.x * (dt0 * bcr + ddv.x) * sz.x;
                float y1 = xc.y * (dt1 * bcr + ddv.y) * sz.y;
                *(float2*)(sh_xz + r * 1024 + c) = make_float2(y0, y1);
            }
        }
        __syncthreads();

        // ---- GEMM3: h = y @ out_proj   [16,512]@[512,256] ----
        // thread: 8 rows x 2 cols; k in chunks of 4
        {
            F2 acc[8];
            #pragma unroll
            for (int i = 0; i < 8; i++) acc[i].f = make_float2(0.f, 0.f);

            const int rbase = ty * 8;
            #pragma unroll 2
            for (int k0 = 0; k0 < DINNER; k0 += 4) {
                F2 w0, w1, w2, w3;
                w0.f = *(const float2*)(Op + (size_t)(k0    ) * DMODEL + tx * 2);
                w1.f = *(const float2*)(Op + (size_t)(k0 + 1) * DMODEL + tx * 2);
                w2.f = *(const float2*)(Op + (size_t)(k0 + 2) * DMODEL + tx * 2);
                w3.f = *(const float2*)(Op + (size_t)(k0 + 3) * DMODEL + tx * 2);
                #pragma unroll
                for (int i = 0; i < 8; i++) {
                    float4 a4 = *(const float4*)(sh_xz + (rbase + i) * 1024 + k0);
                    ffma2(acc[i], bcast2(a4.x), w0);
                    ffma2(acc[i], bcast2(a4.y), w1);
                    ffma2(acc[i], bcast2(a4.z), w2);
                    ffma2(acc[i], bcast2(a4.w), w3);
                }
            }
            #pragma unroll
            for (int i = 0; i < 8; i++)
                *(float2*)(sh_h + (rbase + i) * DMODEL + tx * 2) = acc[i].f;
        }
        __syncthreads();
    }

    // =====================================================================
    // Output head: out = h @ Wo + bo
    // =====================================================================
    if (t < ROWS) {
        float s = 0.f;
        #pragma unroll 8
        for (int m = 0; m < DMODEL; m++)
            s = fmaf(sh_h[t * DMODEL + m], Wo[m], s);
        out[row0 + t] = s + bo[0];
    }
}

// ---------------------------------------------------------------------------
// launch
// ---------------------------------------------------------------------------
extern "C" void kernel_launch(void* const* d_in, const int* in_sizes, int n_in,
                              void* d_out, int out_size)
{
    (void)in_sizes; (void)n_in; (void)out_size;

    const size_t smem_bytes =
        (size_t)(ROWS * DMODEL + ROWS * 2 * DINNER + ROWS * 48 + ROWS) * sizeof(float);

    cudaFuncSetAttribute(mamba_icl_kernel,
                         cudaFuncAttributeMaxDynamicSharedMemorySize,
                         (int)smem_bytes);

    mamba_icl_kernel<<<BATCH / ROWS, NTHREADS, smem_bytes>>>(
        (const float*)d_in[0],   // x
        (const float*)d_in[1],   // Wi
        (const float*)d_in[2],   // bi
        (const float*)d_in[3],   // in_proj_w
        (const float*)d_in[4],   // conv_w
        (const float*)d_in[5],   // conv_b
        (const float*)d_in[6],   // x_proj_w
        (const float*)d_in[7],   // dt_proj_w
        (const float*)d_in[8],   // dt_proj_b
        // d_in[9] = A_log is mathematically dead (h0 = 0, L = 1)
        (const float*)d_in[10],  // D
        (const float*)d_in[11],  // out_proj_w
        (const float*)d_in[12],  // Wo
        (const float*)d_in[13],  // bo
        (float*)d_out);
}

// round 3
// speedup vs baseline: 1.1948x; 1.0681x over previous
#include <cuda_runtime.h>
#include <math.h>

#define NLAYERS 12
#define DMODEL  256
#define DINNER  512
#define DTRANK  16
#define DSTATE  16
#define INDIM   230
#define BATCH   4096
#define ROWS    16
#define NTHREADS 256

// ---------------------------------------------------------------------------
// packed f32x2 FMA (Blackwell FFMA2): d = a*b + d on both lanes
// ---------------------------------------------------------------------------
union F2 { float2 f; unsigned long long u; };

__device__ __forceinline__ void ffma2(F2 &d, const F2 a, const F2 b) {
    asm("fma.rn.f32x2 %0, %1, %2, %0;" : "+l"(d.u) : "l"(a.u), "l"(b.u));
}
__device__ __forceinline__ F2 bcast2(float v) { F2 r; r.f = make_float2(v, v); return r; }

__device__ __forceinline__ float silu_f(float v) {
    return v * (1.0f / (1.0f + __expf(-v)));
}
__device__ __forceinline__ float softplus_f(float v) {
    return (v > 20.0f) ? v : log1pf(__expf(v));
}

// ---------------------------------------------------------------------------
// One block = 16 batch rows; 2 CTAs/SM. Full 12-layer stack out of SMEM.
// SMEM: h[16][256], xz[16][1024], dbl[16][48], bc[16]  (~85 KB)
// ---------------------------------------------------------------------------
extern "C" __global__ void __launch_bounds__(NTHREADS, 2)
mamba_icl_kernel(const float* __restrict__ x,          // [4096,230]
                 const float* __restrict__ Wi,         // [230,256]
                 const float* __restrict__ bi,         // [256]
                 const float* __restrict__ in_proj_w,  // [12,256,1024]
                 const float* __restrict__ conv_w,     // [12,512,4]
                 const float* __restrict__ conv_b,     // [12,512]
                 const float* __restrict__ x_proj_w,   // [12,512,48]
                 const float* __restrict__ dt_proj_w,  // [12,16,512]
                 const float* __restrict__ dt_proj_b,  // [12,512]
                 const float* __restrict__ Dvec,       // [12,512]
                 const float* __restrict__ out_proj_w, // [12,512,256]
                 const float* __restrict__ Wo,         // [256,1]
                 const float* __restrict__ bo,         // [1]
                 float* __restrict__ out)              // [4096,1]
{
    extern __shared__ float sm[];
    float* sh_h   = sm;                         // 16*256  = 4096
    float* sh_xz  = sm + ROWS * DMODEL;         // 16*1024 = 16384
    float* sh_dbl = sh_xz + ROWS * 2 * DINNER;  // 16*48   = 768
    float* sh_bc  = sh_dbl + ROWS * 48;         // 16

    const int t    = threadIdx.x;
    const int row0 = blockIdx.x * ROWS;
    const int tx   = t & 127;   // 128 column groups
    const int ty   = t >> 7;    // 2 row groups of 8 rows

    // =====================================================================
    // Stage x rows into SMEM (coalesced), reuse sh_xz as scratch
    // =====================================================================
    float* sh_x = sh_xz;
    for (int idx = t; idx < ROWS * INDIM; idx += NTHREADS) {
        int r = idx / INDIM, c = idx - r * INDIM;
        sh_x[r * INDIM + c] = x[(size_t)(row0 + r) * INDIM + c];
    }
    __syncthreads();

    // =====================================================================
    // Input projection: h = x @ Wi + bi   [16,230]@[230,256]
    // =====================================================================
    {
        F2 acc[8];
        #pragma unroll
        for (int i = 0; i < 8; i++) acc[i].f = make_float2(0.f, 0.f);

        const int rbase = ty * 8;
        #pragma unroll 2
        for (int k0 = 0; k0 < INDIM; k0 += 2) {
            F2 w0; w0.f = *(const float2*)(Wi + (size_t)k0 * DMODEL + tx * 2);
            F2 w1; w1.f = *(const float2*)(Wi + (size_t)(k0 + 1) * DMODEL + tx * 2);
            #pragma unroll
            for (int i = 0; i < 8; i++) {
                float2 a2 = *(const float2*)(sh_x + (rbase + i) * INDIM + k0);
                ffma2(acc[i], bcast2(a2.x), w0);
                ffma2(acc[i], bcast2(a2.y), w1);
            }
        }
        __syncthreads();   // done reading sh_x before anything overwrites sh_xz
        float2 bv = *(const float2*)(bi + tx * 2);
        #pragma unroll
        for (int i = 0; i < 8; i++) {
            sh_h[(rbase + i) * DMODEL + tx * 2]     = acc[i].f.x + bv.x;
            sh_h[(rbase + i) * DMODEL + tx * 2 + 1] = acc[i].f.y + bv.y;
        }
    }
    __syncthreads();

    // GEMM2 thread mapping (constant across layers)
    const int o0 = 2 * t;                 // first F2 output (elements o0, o0+1)
    const int r0 = o0 / 48, j0 = o0 - r0 * 48;
    const int o1 = 2 * t + 512;           // second F2 output, threads t<128 only
    const int r1 = o1 / 48, j1 = o1 - r1 * 48;

    // =====================================================================
    // 12 Mamba layers
    // =====================================================================
    for (int l = 0; l < NLAYERS; l++) {
        const float* Wp = in_proj_w  + (size_t)l * DMODEL * 2 * DINNER;
        const float* Cw = conv_w     + (size_t)l * DINNER * 4;
        const float* Cb = conv_b     + (size_t)l * DINNER;
        const float* Xp = x_proj_w   + (size_t)l * DINNER * 48;
        const float* Dw = dt_proj_w  + (size_t)l * DTRANK * DINNER;
        const float* Db = dt_proj_b  + (size_t)l * DINNER;
        const float* Dd = Dvec       + (size_t)l * DINNER;
        const float* Op = out_proj_w + (size_t)l * DINNER * DMODEL;

        // ---- GEMM1 + fused conv/silu epilogue:  [16,256]@[256,1024] ----
        // thread: 8 rows x 8 cols; k-step 2, distance-1 weight prefetch
        {
            F2 acc[8][4];
            #pragma unroll
            for (int i = 0; i < 8; i++)
                #pragma unroll
                for (int j = 0; j < 4; j++) acc[i][j].f = make_float2(0.f, 0.f);

            const int rbase = ty * 8;
            const float* wp = Wp + tx * 8;

            float4 nw0 = *(const float4*)(wp);
            float4 nw1 = *(const float4*)(wp + 4);
            float4 nw2 = *(const float4*)(wp + 1024);
            float4 nw3 = *(const float4*)(wp + 1028);

            for (int k0 = 0; k0 < DMODEL; k0 += 2) {
                float4 w00 = nw0, w01 = nw1, w10 = nw2, w11 = nw3;
                // prefetch next k-pair (wraps to 0 on last iter: safe, discarded)
                const int kn = (k0 + 2) & (DMODEL - 1);
                const float* wn = wp + (size_t)kn * 1024;
                nw0 = *(const float4*)(wn);
                nw1 = *(const float4*)(wn + 4);
                nw2 = *(const float4*)(wn + 1024);
                nw3 = *(const float4*)(wn + 1028);

                F2 b00, b01, b02, b03, b10, b11, b12, b13;
                b00.f = make_float2(w00.x, w00.y); b01.f = make_float2(w00.z, w00.w);
                b02.f = make_float2(w01.x, w01.y); b03.f = make_float2(w01.z, w01.w);
                b10.f = make_float2(w10.x, w10.y); b11.f = make_float2(w10.z, w10.w);
                b12.f = make_float2(w11.x, w11.y); b13.f = make_float2(w11.z, w11.w);
                #pragma unroll
                for (int i = 0; i < 8; i++) {
                    float2 a2 = *(const float2*)(sh_h + (rbase + i) * DMODEL + k0);
                    F2 ax = bcast2(a2.x), ay = bcast2(a2.y);
                    ffma2(acc[i][0], ax, b00);
                    ffma2(acc[i][1], ax, b01);
                    ffma2(acc[i][2], ax, b02);
                    ffma2(acc[i][3], ax, b03);
                    ffma2(acc[i][0], ay, b10);
                    ffma2(acc[i][1], ay, b11);
                    ffma2(acc[i][2], ay, b12);
                    ffma2(acc[i][3], ay, b13);
                }
            }
            // epilogue: fused (conv tap3 + bias + silu) on xr half, silu on z half
            if (tx < 64) {
                #pragma unroll
                for (int j = 0; j < 4; j++) {
                    int c = tx * 8 + j * 2;
                    float cw0 = Cw[c * 4 + 3],       cb0 = Cb[c];
                    float cw1 = Cw[(c + 1) * 4 + 3], cb1 = Cb[c + 1];
                    #pragma unroll
                    for (int i = 0; i < 8; i++) {
                        float v0 = silu_f(acc[i][j].f.x * cw0 + cb0);
                        float v1 = silu_f(acc[i][j].f.y * cw1 + cb1);
                        *(float2*)(sh_xz + (ty * 8 + i) * 1024 + c) = make_float2(v0, v1);
                    }
                }
            } else {
                #pragma unroll
                for (int j = 0; j < 4; j++) {
                    int c = tx * 8 + j * 2;
                    #pragma unroll
                    for (int i = 0; i < 8; i++) {
                        float v0 = silu_f(acc[i][j].f.x);
                        float v1 = silu_f(acc[i][j].f.y);
                        *(float2*)(sh_xz + (ty * 8 + i) * 1024 + c) = make_float2(v0, v1);
                    }
                }
            }
        }
        __syncthreads();

        // ---- GEMM2: dbl = xc @ x_proj  [16,512]@[512,48] ----
        // 384 F2 outputs; thread t owns F2 #t, threads t<128 also F2 #(t+256)
        {
            F2 a0; a0.f = make_float2(0.f, 0.f);
            F2 a1; a1.f = make_float2(0.f, 0.f);
            const bool two = (t < 128);
            #pragma unroll 2
            for (int k = 0; k < DINNER; k += 4) {
                float4 v0 = *(const float4*)(sh_xz + r0 * 1024 + k);
                F2 w;
                w.f = *(const float2*)(Xp + (size_t)k * 48 + j0);
                ffma2(a0, bcast2(v0.x), w);
                w.f = *(const float2*)(Xp + (size_t)(k + 1) * 48 + j0);
                ffma2(a0, bcast2(v0.y), w);
                w.f = *(const float2*)(Xp + (size_t)(k + 2) * 48 + j0);
                ffma2(a0, bcast2(v0.z), w);
                w.f = *(const float2*)(Xp + (size_t)(k + 3) * 48 + j0);
                ffma2(a0, bcast2(v0.w), w);
                if (two) {
                    float4 v1 = *(const float4*)(sh_xz + r1 * 1024 + k);
                    w.f = *(const float2*)(Xp + (size_t)k * 48 + j1);
                    ffma2(a1, bcast2(v1.x), w);
                    w.f = *(const float2*)(Xp + (size_t)(k + 1) * 48 + j1);
                    ffma2(a1, bcast2(v1.y), w);
                    w.f = *(const float2*)(Xp + (size_t)(k + 2) * 48 + j1);
                    ffma2(a1, bcast2(v1.z), w);
                    w.f = *(const float2*)(Xp + (size_t)(k + 3) * 48 + j1);
                    ffma2(a1, bcast2(v1.w), w);
                }
            }
            *(float2*)(sh_dbl + o0) = a0.f;
            if (two) *(float2*)(sh_dbl + o1) = a1.f;
        }
        __syncthreads();

        // ---- bc[r] = dot(B, C) over D_STATE ----
        if (t < ROWS) {
            float s = 0.f;
            #pragma unroll
            for (int j = 0; j < DSTATE; j++)
                s = fmaf(sh_dbl[t * 48 + DTRANK + j], sh_dbl[t * 48 + DTRANK + DSTATE + j], s);
            sh_bc[t] = s;
        }
        __syncthreads();

        // ---- fused dt projection + softplus + gating (y in place of xc) ----
        // thread owns columns {2t, 2t+1}; dt weights hoisted to registers
        {
            const int c = t * 2;
            F2 dw[DTRANK];
            #pragma unroll
            for (int j = 0; j < DTRANK; j++)
                dw[j].f = *(const float2*)(Dw + j * DINNER + c);
            const float2 dbv = *(const float2*)(Db + c);
            const float2 ddv = *(const float2*)(Dd + c);

            #pragma unroll 2
            for (int r = 0; r < ROWS; r++) {
                float4 d0 = *(const float4*)(sh_dbl + r * 48);
                float4 d1 = *(const float4*)(sh_dbl + r * 48 + 4);
                float4 d2 = *(const float4*)(sh_dbl + r * 48 + 8);
                float4 d3 = *(const float4*)(sh_dbl + r * 48 + 12);
                F2 sdt; sdt.f = dbv;
                ffma2(sdt, bcast2(d0.x), dw[0]);
                ffma2(sdt, bcast2(d0.y), dw[1]);
                ffma2(sdt, bcast2(d0.z), dw[2]);
                ffma2(sdt, bcast2(d0.w), dw[3]);
                ffma2(sdt, bcast2(d1.x), dw[4]);
                ffma2(sdt, bcast2(d1.y), dw[5]);
                ffma2(sdt, bcast2(d1.z), dw[6]);
                ffma2(sdt, bcast2(d1.w), dw[7]);
                ffma2(sdt, bcast2(d2.x), dw[8]);
                ffma2(sdt, bcast2(d2.y), dw[9]);
                ffma2(sdt, bcast2(d2.z), dw[10]);
                ffma2(sdt, bcast2(d2.w), dw[11]);
                ffma2(sdt, bcast2(d3.x), dw[12]);
                ffma2(sdt, bcast2(d3.y), dw[13]);
                ffma2(sdt, bcast2(d3.z), dw[14]);
                ffma2(sdt, bcast2(d3.w), dw[15]);
                float dt0 = softplus_f(sdt.f.x);
                float dt1 = softplus_f(sdt.f.y);
                float bcr = sh_bc[r];
                float2 xc = *(const float2*)(sh_xz + r * 1024 + c);
                float2 sz = *(const float2*)(sh_xz + r * 1024 + DINNER + c);  // already silu'd
                float y0 = xc.x * (dt0 * bcr + ddv.x) * sz.x;
                float y1 = xc.y * (dt1 * bcr + ddv.y) * sz.y;
                *(float2*)(sh_xz + r * 1024 + c) = make_float2(y0, y1);
            }
        }
        __syncthreads();

        // ---- GEMM3: h = y @ out_proj  [16,512]@[512,256] ----
        // thread: 8 rows x 2 cols; k-step 4, distance-1 weight prefetch
        {
            F2 acc[8];
            #pragma unroll
            for (int i = 0; i < 8; i++) acc[i].f = make_float2(0.f, 0.f);

            const int rbase = ty * 8;
            const float* op = Op + tx * 2;

            F2 nw0, nw1, nw2, nw3;
            nw0.f = *(const float2*)(op);
            nw1.f = *(const float2*)(op + DMODEL);
            nw2.f = *(const float2*)(op + 2 * DMODEL);
            nw3.f = *(const float2*)(op + 3 * DMODEL);

            for (int k0 = 0; k0 < DINNER; k0 += 4) {
                F2 w0 = nw0, w1 = nw1, w2 = nw2, w3 = nw3;
                const int kn = (k0 + 4) & (DINNER - 1);
                const float* on = op + (size_t)kn * DMODEL;
                nw0.f = *(const float2*)(on);
                nw1.f = *(const float2*)(on + DMODEL);
                nw2.f = *(const float2*)(on + 2 * DMODEL);
                nw3.f = *(const float2*)(on + 3 * DMODEL);
                #pragma unroll
                for (int i = 0; i < 8; i++) {
                    float4 a4 = *(const float4*)(sh_xz + (rbase + i) * 1024 + k0);
                    ffma2(acc[i], bcast2(a4.x), w0);
                    ffma2(acc[i], bcast2(a4.y), w1);
                    ffma2(acc[i], bcast2(a4.z), w2);
                    ffma2(acc[i], bcast2(a4.w), w3);
                }
            }
            #pragma unroll
            for (int i = 0; i < 8; i++)
                *(float2*)(sh_h + (rbase + i) * DMODEL + tx * 2) = acc[i].f;
        }
        __syncthreads();
    }

    // =====================================================================
    // Output head: out = h @ Wo + bo
    // =====================================================================
    if (t < ROWS) {
        float s = 0.f;
        #pragma unroll 8
        for (int m = 0; m < DMODEL; m++)
            s = fmaf(sh_h[t * DMODEL + m], Wo[m], s);
        out[row0 + t] = s + bo[0];
    }
}

// ---------------------------------------------------------------------------
// launch
// ---------------------------------------------------------------------------
extern "C" void kernel_launch(void* const* d_in, const int* in_sizes, int n_in,
                              void* d_out, int out_size)
{
    (void)in_sizes; (void)n_in; (void)out_size;

    const size_t smem_bytes =
        (size_t)(ROWS * DMODEL + ROWS * 2 * DINNER + ROWS * 48 + ROWS) * sizeof(float);

    cudaFuncSetAttribute(mamba_icl_kernel,
                         cudaFuncAttributeMaxDynamicSharedMemorySize,
                         (int)smem_bytes);

    mamba_icl_kernel<<<BATCH / ROWS, NTHREADS, smem_bytes>>>(
        (const float*)d_in[0],   // x
        (const float*)d_in[1],   // Wi
        (const float*)d_in[2],   // bi
        (const float*)d_in[3],   // in_proj_w
        (const float*)d_in[4],   // conv_w
        (const float*)d_in[5],   // conv_b
        (const float*)d_in[6],   // x_proj_w
        (const float*)d_in[7],   // dt_proj_w
        (const float*)d_in[8],   // dt_proj_b
        // d_in[9] = A_log is mathematically dead (h0 = 0, L = 1)
        (const float*)d_in[10],  // D
        (const float*)d_in[11],  // out_proj_w
        (const float*)d_in[12],  // Wo
        (const float*)d_in[13],  // bo
        (float*)d_out);
}

// round 4
// speedup vs baseline: 2.0788x; 1.7399x over previous
#include <cuda_runtime.h>
#include <cuda_bf16.h>
#include <math.h>

#define NLAYERS 12
#define DMODEL  256
#define DINNER  512
#define DTRANK  16
#define DSTATE  16
#define INDIM   230
#define BATCH   4096
#define ROWS    16
#define NTHREADS 256

#define KT1 16    // 256/16 k-tiles, GEMM1
#define NT1 128   // 1024/8 n-tiles, GEMM1
#define KT3 32    // 512/16 k-tiles, GEMM3
#define NT3 32    // 256/8  n-tiles, GEMM3
#define NG1 (NLAYERS*KT1*NT1*32)   // 786432
#define NG3 (NLAYERS*KT3*NT3*32)   // 393216

// fragment-packed weights (hi/lo bf16 split) — __device__ scratch (allowed)
__device__ uint2 g_Whi1[NG1];
__device__ uint2 g_Wlo1[NG1];
__device__ uint2 g_Whi3[NG3];
__device__ uint2 g_Wlo3[NG3];

// ---------------------------------------------------------------------------
union F2 { float2 f; unsigned long long u; };
__device__ __forceinline__ void ffma2(F2 &d, const F2 a, const F2 b) {
    asm("fma.rn.f32x2 %0, %1, %2, %0;" : "+l"(d.u) : "l"(a.u), "l"(b.u));
}
__device__ __forceinline__ F2 bcast2(float v) { F2 r; r.f = make_float2(v, v); return r; }

__device__ __forceinline__ float silu_f(float v) {
    return v * (1.0f / (1.0f + __expf(-v)));
}
__device__ __forceinline__ float softplus_f(float v) {
    return (v > 20.0f) ? v : log1pf(__expf(v));
}

// split (x,y) fp32 -> packed bf16x2 hi + packed bf16x2 lo  (x in low half)
__device__ __forceinline__ void split2(float x, float y, unsigned &hi, unsigned &lo) {
    __nv_bfloat162 h = __floats2bfloat162_rn(x, y);
    float rx = x - __bfloat162float(__low2bfloat16(h));
    float ry = y - __bfloat162float(__high2bfloat16(h));
    __nv_bfloat162 l2 = __floats2bfloat162_rn(rx, ry);
    hi = *reinterpret_cast<unsigned*>(&h);
    lo = *reinterpret_cast<unsigned*>(&l2);
}

// m16n8k16 bf16 mma, D(f32) += A(bf16) * B(bf16)
__device__ __forceinline__ void mma_bf16(float (&d)[4], const unsigned (&a)[4],
                                         unsigned b0, unsigned b1) {
    asm volatile(
        "mma.sync.aligned.m16n8k16.row.col.f32.bf16.bf16.f32 "
        "{%0,%1,%2,%3}, {%4,%5,%6,%7}, {%8,%9}, {%0,%1,%2,%3};"
        : "+f"(d[0]), "+f"(d[1]), "+f"(d[2]), "+f"(d[3])
        : "r"(a[0]), "r"(a[1]), "r"(a[2]), "r"(a[3]), "r"(b0), "r"(b1));
}

// ---------------------------------------------------------------------------
// prep: repack in_proj / out_proj into mma B-fragment order, bf16 hi/lo split
// B frag (col-major 16x8): lane l -> n = l/4, k0 = (l%4)*2; reg0=(k0,k0+1), reg1=(k0+8,k0+9)
// ---------------------------------------------------------------------------
extern "C" __global__ void prep_kernel(const float* __restrict__ in_proj_w,
                                       const float* __restrict__ out_proj_w)
{
    int gid = blockIdx.x * blockDim.x + threadIdx.x;
    if (gid < NG1) {
        int lane = gid & 31; int rest = gid >> 5;
        int nt = rest % NT1; rest /= NT1;
        int kt = rest % KT1; int l = rest / KT1;
        int n  = nt * 8 + (lane >> 2);
        int k0 = kt * 16 + (lane & 3) * 2;
        const float* W = in_proj_w + (size_t)l * DMODEL * 1024;
        float v0 = W[(size_t)(k0    ) * 1024 + n];
        float v1 = W[(size_t)(k0 + 1) * 1024 + n];
        float v2 = W[(size_t)(k0 + 8) * 1024 + n];
        float v3 = W[(size_t)(k0 + 9) * 1024 + n];
        unsigned h0, l0, h1, l1;
        split2(v0, v1, h0, l0);
        split2(v2, v3, h1, l1);
        g_Whi1[gid] = make_uint2(h0, h1);
        g_Wlo1[gid] = make_uint2(l0, l1);
    } else if (gid < NG1 + NG3) {
        int g = gid - NG1;
        int lane = g & 31; int rest = g >> 5;
        int nt = rest % NT3; rest /= NT3;
        int kt = rest % KT3; int l = rest / KT3;
        int n  = nt * 8 + (lane >> 2);
        int k0 = kt * 16 + (lane & 3) * 2;
        const float* W = out_proj_w + (size_t)l * DINNER * DMODEL;
        float v0 = W[(size_t)(k0    ) * DMODEL + n];
        float v1 = W[(size_t)(k0 + 1) * DMODEL + n];
        float v2 = W[(size_t)(k0 + 8) * DMODEL + n];
        float v3 = W[(size_t)(k0 + 9) * DMODEL + n];
        unsigned h0, l0, h1, l1;
        split2(v0, v1, h0, l0);
        split2(v2, v3, h1, l1);
        g_Whi3[g] = make_uint2(h0, h1);
        g_Wlo3[g] = make_uint2(l0, l1);
    }
}

// ---------------------------------------------------------------------------
// main: one block = 16 batch rows, 2 CTAs/SM; mma for GEMM1/GEMM3
// SMEM: h[16][256], xz[16][1024], dbl[16][48], bc[16]  (~85 KB)
// ---------------------------------------------------------------------------
extern "C" __global__ void __launch_bounds__(NTHREADS, 2)
mamba_icl_kernel(const float* __restrict__ x,
                 const float* __restrict__ Wi,
                 const float* __restrict__ bi,
                 const float* __restrict__ conv_w,
                 const float* __restrict__ conv_b,
                 const float* __restrict__ x_proj_w,
                 const float* __restrict__ dt_proj_w,
                 const float* __restrict__ dt_proj_b,
                 const float* __restrict__ Dvec,
                 const float* __restrict__ Wo,
                 const float* __restrict__ bo,
                 float* __restrict__ out)
{
    extern __shared__ float sm[];
    float* sh_h   = sm;                         // 16*256
    float* sh_xz  = sm + ROWS * DMODEL;         // 16*1024
    float* sh_dbl = sh_xz + ROWS * 2 * DINNER;  // 16*48
    float* sh_bc  = sh_dbl + ROWS * 48;         // 16

    const int t    = threadIdx.x;
    const int row0 = blockIdx.x * ROWS;
    const int tx   = t & 127;
    const int ty   = t >> 7;
    const int wid  = t >> 5;       // warp 0..7
    const int lane = t & 31;
    const int fr   = lane >> 2;        // fragment row 0..7
    const int fc   = (lane & 3) * 2;   // fragment col pair

    // ---- stage x, input projection (fp32 FFMA2, one-time) ----
    float* sh_x = sh_xz;
    for (int idx = t; idx < ROWS * INDIM; idx += NTHREADS) {
        int r = idx / INDIM, c = idx - r * INDIM;
        sh_x[r * INDIM + c] = x[(size_t)(row0 + r) * INDIM + c];
    }
    __syncthreads();
    {
        F2 acc[8];
        #pragma unroll
        for (int i = 0; i < 8; i++) acc[i].f = make_float2(0.f, 0.f);
        const int rbase = ty * 8;
        #pragma unroll 2
        for (int k0 = 0; k0 < INDIM; k0 += 2) {
            F2 w0; w0.f = *(const float2*)(Wi + (size_t)k0 * DMODEL + tx * 2);
            F2 w1; w1.f = *(const float2*)(Wi + (size_t)(k0 + 1) * DMODEL + tx * 2);
            #pragma unroll
            for (int i = 0; i < 8; i++) {
                float2 a2 = *(const float2*)(sh_x + (rbase + i) * INDIM + k0);
                ffma2(acc[i], bcast2(a2.x), w0);
                ffma2(acc[i], bcast2(a2.y), w1);
            }
        }
        __syncthreads();
        float2 bv = *(const float2*)(bi + tx * 2);
        #pragma unroll
        for (int i = 0; i < 8; i++) {
            sh_h[(rbase + i) * DMODEL + tx * 2]     = acc[i].f.x + bv.x;
            sh_h[(rbase + i) * DMODEL + tx * 2 + 1] = acc[i].f.y + bv.y;
        }
    }
    __syncthreads();

    // GEMM2 mapping (constant)
    const int o0 = 2 * t;
    const int r0 = o0 / 48, j0 = o0 - r0 * 48;
    const int o1 = 2 * t + 512;
    const int r1 = o1 / 48, j1 = o1 - r1 * 48;

    for (int l = 0; l < NLAYERS; l++) {
        const float* Cw = conv_w    + (size_t)l * DINNER * 4;
        const float* Cb = conv_b    + (size_t)l * DINNER;
        const float* Xp = x_proj_w  + (size_t)l * DINNER * 48;
        const float* Dw = dt_proj_w + (size_t)l * DTRANK * DINNER;
        const float* Db = dt_proj_b + (size_t)l * DINNER;
        const float* Dd = Dvec      + (size_t)l * DINNER;

        // ================= GEMM1 via mma: [16,256]@[256,1024] =================
        // warp owns 16 n-tiles (128 cols); 3-term bf16 split per tile
        {
            float acc[16][4];
            #pragma unroll
            for (int nt = 0; nt < 16; nt++)
                #pragma unroll
                for (int j = 0; j < 4; j++) acc[nt][j] = 0.f;

            for (int kt = 0; kt < KT1; kt++) {
                float2 a00 = *(const float2*)(sh_h + fr * DMODEL + kt * 16 + fc);
                float2 a10 = *(const float2*)(sh_h + (fr + 8) * DMODEL + kt * 16 + fc);
                float2 a01 = *(const float2*)(sh_h + fr * DMODEL + kt * 16 + fc + 8);
                float2 a11 = *(const float2*)(sh_h + (fr + 8) * DMODEL + kt * 16 + fc + 8);
                unsigned ahi[4], alo[4];
                split2(a00.x, a00.y, ahi[0], alo[0]);
                split2(a10.x, a10.y, ahi[1], alo[1]);
                split2(a01.x, a01.y, ahi[2], alo[2]);
                split2(a11.x, a11.y, ahi[3], alo[3]);

                const uint2* bh = g_Whi1 + (((size_t)l * KT1 + kt) * NT1 + wid * 16) * 32 + lane;
                const uint2* bl = g_Wlo1 + (((size_t)l * KT1 + kt) * NT1 + wid * 16) * 32 + lane;
                #pragma unroll
                for (int nt = 0; nt < 16; nt++) {
                    uint2 Bh = bh[nt * 32];
                    uint2 Bl = bl[nt * 32];
                    mma_bf16(acc[nt], ahi, Bh.x, Bh.y);
                    mma_bf16(acc[nt], alo, Bh.x, Bh.y);
                    mma_bf16(acc[nt], ahi, Bl.x, Bl.y);
                }
            }
            // epilogue: warps 0-3 -> xr half (conv tap3+bias+silu), warps 4-7 -> silu(z)
            if (wid < 4) {
                #pragma unroll
                for (int nt = 0; nt < 16; nt++) {
                    int c = wid * 128 + nt * 8 + fc;
                    float cw0 = Cw[c * 4 + 3],       cb0 = Cb[c];
                    float cw1 = Cw[(c + 1) * 4 + 3], cb1 = Cb[c + 1];
                    float v00 = silu_f(acc[nt][0] * cw0 + cb0);
                    float v01 = silu_f(acc[nt][1] * cw1 + cb1);
                    float v10 = silu_f(acc[nt][2] * cw0 + cb0);
                    float v11 = silu_f(acc[nt][3] * cw1 + cb1);
                    *(float2*)(sh_xz + fr * 1024 + c)       = make_float2(v00, v01);
                    *(float2*)(sh_xz + (fr + 8) * 1024 + c) = make_float2(v10, v11);
                }
            } else {
                #pragma unroll
                for (int nt = 0; nt < 16; nt++) {
                    int c = wid * 128 + nt * 8 + fc;   // >= 512: z region
                    float v00 = silu_f(acc[nt][0]);
                    float v01 = silu_f(acc[nt][1]);
                    float v10 = silu_f(acc[nt][2]);
                    float v11 = silu_f(acc[nt][3]);
                    *(float2*)(sh_xz + fr * 1024 + c)       = make_float2(v00, v01);
                    *(float2*)(sh_xz + (fr + 8) * 1024 + c) = make_float2(v10, v11);
                }
            }
        }
        __syncthreads();

        // ================= GEMM2 (fp32): dbl = xc @ x_proj [16,512]@[512,48] ===
        {
            F2 a0; a0.f = make_float2(0.f, 0.f);
            F2 a1; a1.f = make_float2(0.f, 0.f);
            const bool two = (t < 128);
            #pragma unroll 2
            for (int k = 0; k < DINNER; k += 4) {
                float4 v0 = *(const float4*)(sh_xz + r0 * 1024 + k);
                F2 w;
                w.f = *(const float2*)(Xp + (size_t)k * 48 + j0);
                ffma2(a0, bcast2(v0.x), w);
                w.f = *(const float2*)(Xp + (size_t)(k + 1) * 48 + j0);
                ffma2(a0, bcast2(v0.y), w);
                w.f = *(const float2*)(Xp + (size_t)(k + 2) * 48 + j0);
                ffma2(a0, bcast2(v0.z), w);
                w.f = *(const float2*)(Xp + (size_t)(k + 3) * 48 + j0);
                ffma2(a0, bcast2(v0.w), w);
                if (two) {
                    float4 v1 = *(const float4*)(sh_xz + r1 * 1024 + k);
                    w.f = *(const float2*)(Xp + (size_t)k * 48 + j1);
                    ffma2(a1, bcast2(v1.x), w);
                    w.f = *(const float2*)(Xp + (size_t)(k + 1) * 48 + j1);
                    ffma2(a1, bcast2(v1.y), w);
                    w.f = *(const float2*)(Xp + (size_t)(k + 2) * 48 + j1);
                    ffma2(a1, bcast2(v1.z), w);
                    w.f = *(const float2*)(Xp + (size_t)(k + 3) * 48 + j1);
                    ffma2(a1, bcast2(v1.w), w);
                }
            }
            *(float2*)(sh_dbl + o0) = a0.f;
            if (two) *(float2*)(sh_dbl + o1) = a1.f;
        }
        __syncthreads();

        // ---- bc[r] = dot(B, C) ----
        if (t < ROWS) {
            float s = 0.f;
            #pragma unroll
            for (int j = 0; j < DSTATE; j++)
                s = fmaf(sh_dbl[t * 48 + DTRANK + j], sh_dbl[t * 48 + DTRANK + DSTATE + j], s);
            sh_bc[t] = s;
        }
        __syncthreads();

        // ---- fused dt projection + softplus + gating ----
        {
            const int c = t * 2;
            F2 dw[DTRANK];
            #pragma unroll
            for (int j = 0; j < DTRANK; j++)
                dw[j].f = *(const float2*)(Dw + j * DINNER + c);
            const float2 dbv = *(const float2*)(Db + c);
            const float2 ddv = *(const float2*)(Dd + c);

            #pragma unroll 2
            for (int r = 0; r < ROWS; r++) {
                float4 d0 = *(const float4*)(sh_dbl + r * 48);
                float4 d1 = *(const float4*)(sh_dbl + r * 48 + 4);
                float4 d2 = *(const float4*)(sh_dbl + r * 48 + 8);
                float4 d3 = *(const float4*)(sh_dbl + r * 48 + 12);
                F2 sdt; sdt.f = dbv;
                ffma2(sdt, bcast2(d0.x), dw[0]);  ffma2(sdt, bcast2(d0.y), dw[1]);
                ffma2(sdt, bcast2(d0.z), dw[2]);  ffma2(sdt, bcast2(d0.w), dw[3]);
                ffma2(sdt, bcast2(d1.x), dw[4]);  ffma2(sdt, bcast2(d1.y), dw[5]);
                ffma2(sdt, bcast2(d1.z), dw[6]);  ffma2(sdt, bcast2(d1.w), dw[7]);
                ffma2(sdt, bcast2(d2.x), dw[8]);  ffma2(sdt, bcast2(d2.y), dw[9]);
                ffma2(sdt, bcast2(d2.z), dw[10]); ffma2(sdt, bcast2(d2.w), dw[11]);
                ffma2(sdt, bcast2(d3.x), dw[12]); ffma2(sdt, bcast2(d3.y), dw[13]);
                ffma2(sdt, bcast2(d3.z), dw[14]); ffma2(sdt, bcast2(d3.w), dw[15]);
                float dt0 = softplus_f(sdt.f.x);
                float dt1 = softplus_f(sdt.f.y);
                float bcr = sh_bc[r];
                float2 xc = *(const float2*)(sh_xz + r * 1024 + c);
                float2 sz = *(const float2*)(sh_xz + r * 1024 + DINNER + c);
                float y0 = xc.x * (dt0 * bcr + ddv.x) * sz.x;
                float y1 = xc.y * (dt1 * bcr + ddv.y) * sz.y;
                *(float2*)(sh_xz + r * 1024 + c) = make_float2(y0, y1);
            }
        }
        __syncthreads();

        // ================= GEMM3 via mma: h = y @ out_proj [16,512]@[512,256] ==
        {
            float acc[4][4];
            #pragma unroll
            for (int nt = 0; nt < 4; nt++)
                #pragma unroll
                for (int j = 0; j < 4; j++) acc[nt][j] = 0.f;

            for (int kt = 0; kt < KT3; kt++) {
                float2 a00 = *(const float2*)(sh_xz + fr * 1024 + kt * 16 + fc);
                float2 a10 = *(const float2*)(sh_xz + (fr + 8) * 1024 + kt * 16 + fc);
                float2 a01 = *(const float2*)(sh_xz + fr * 1024 + kt * 16 + fc + 8);
                float2 a11 = *(const float2*)(sh_xz + (fr + 8) * 1024 + kt * 16 + fc + 8);
                unsigned ahi[4], alo[4];
                split2(a00.x, a00.y, ahi[0], alo[0]);
                split2(a10.x, a10.y, ahi[1], alo[1]);
                split2(a01.x, a01.y, ahi[2], alo[2]);
                split2(a11.x, a11.y, ahi[3], alo[3]);

                const uint2* bh = g_Whi3 + (((size_t)l * KT3 + kt) * NT3 + wid * 4) * 32 + lane;
                const uint2* bl = g_Wlo3 + (((size_t)l * KT3 + kt) * NT3 + wid * 4) * 32 + lane;
                #pragma unroll
                for (int nt = 0; nt < 4; nt++) {
                    uint2 Bh = bh[nt * 32];
                    uint2 Bl = bl[nt * 32];
                    mma_bf16(acc[nt], ahi, Bh.x, Bh.y);
                    mma_bf16(acc[nt], alo, Bh.x, Bh.y);
                    mma_bf16(acc[nt], ahi, Bl.x, Bl.y);
                }
            }
            __syncthreads();   // all reads of sh_xz done before sh_h rewrite readers
            #pragma unroll
            for (int nt = 0; nt < 4; nt++) {
                int c = wid * 32 + nt * 8 + fc;
                *(float2*)(sh_h + fr * DMODEL + c)       = make_float2(acc[nt][0], acc[nt][1]);
                *(float2*)(sh_h + (fr + 8) * DMODEL + c) = make_float2(acc[nt][2], acc[nt][3]);
            }
        }
        __syncthreads();
    }

    // ---- output head ----
    if (t < ROWS) {
        float s = 0.f;
        #pragma unroll 8
        for (int m = 0; m < DMODEL; m++)
            s = fmaf(sh_h[t * DMODEL + m], Wo[m], s);
        out[row0 + t] = s + bo[0];
    }
}

// ---------------------------------------------------------------------------
extern "C" void kernel_launch(void* const* d_in, const int* in_sizes, int n_in,
                              void* d_out, int out_size)
{
    (void)in_sizes; (void)n_in; (void)out_size;

    prep_kernel<<<(NG1 + NG3 + 255) / 256, 256>>>(
        (const float*)d_in[3],    // in_proj_w
        (const float*)d_in[11]);  // out_proj_w

    const size_t smem_bytes =
        (size_t)(ROWS * DMODEL + ROWS * 2 * DINNER + ROWS * 48 + ROWS) * sizeof(float);

    cudaFuncSetAttribute(mamba_icl_kernel,
                         cudaFuncAttributeMaxDynamicSharedMemorySize,
                         (int)smem_bytes);

    mamba_icl_kernel<<<BATCH / ROWS, NTHREADS, smem_bytes>>>(
        (const float*)d_in[0],   // x
        (const float*)d_in[1],   // Wi
        (const float*)d_in[2],   // bi
        (const float*)d_in[4],   // conv_w
        (const float*)d_in[5],   // conv_b
        (const float*)d_in[6],   // x_proj_w
        (const float*)d_in[7],   // dt_proj_w
        (const float*)d_in[8],   // dt_proj_b
        // d_in[9] = A_log dead (h0 = 0, L = 1)
        (const float*)d_in[10],  // D
        (const float*)d_in[12],  // Wo
        (const float*)d_in[13],  // bo
        (float*)d_out);
}

// round 5
// speedup vs baseline: 3.3703x; 1.6212x over previous
#include <cuda_runtime.h>
#include <cuda_bf16.h>
#include <math.h>

#define NLAYERS 12
#define DMODEL  256
#define DINNER  512
#define DTRANK  16
#define DSTATE  16
#define INDIM   230
#define BATCH   4096
#define ROWS    16
#define NTHREADS 256

#define KT1 16    // 256/16 k-tiles, GEMM1
#define NT1 128   // 1024/8 n-tiles, GEMM1
#define KT3 32    // 512/16 k-tiles, GEMM3
#define NT3 32    // 256/8  n-tiles, GEMM3
#define KT2 32    // 512/16 k-tiles, GEMM2
#define NT2 6     // 48/8   n-tiles, GEMM2
#define NG1 (NLAYERS*KT1*NT1*32)   // 786432
#define NG3 (NLAYERS*KT3*NT3*32)   // 393216
#define NG2 (NLAYERS*KT2*NT2*32)   // 73728

// fragment-packed weights (hi/lo bf16 split) — __device__ scratch (allowed)
__device__ uint2 g_Whi1[NG1];
__device__ uint2 g_Wlo1[NG1];
__device__ uint2 g_Whi3[NG3];
__device__ uint2 g_Wlo3[NG3];
__device__ uint2 g_Whi2[NG2];
__device__ uint2 g_Wlo2[NG2];

// ---------------------------------------------------------------------------
union F2 { float2 f; unsigned long long u; };
__device__ __forceinline__ void ffma2(F2 &d, const F2 a, const F2 b) {
    asm("fma.rn.f32x2 %0, %1, %2, %0;" : "+l"(d.u) : "l"(a.u), "l"(b.u));
}
__device__ __forceinline__ F2 bcast2(float v) { F2 r; r.f = make_float2(v, v); return r; }

__device__ __forceinline__ float silu_f(float v) {
    return v * (1.0f / (1.0f + __expf(-v)));
}
__device__ __forceinline__ float softplus_f(float v) {
    return (v > 20.0f) ? v : log1pf(__expf(v));
}

// split (x,y) fp32 -> packed bf16x2 hi + packed bf16x2 lo  (x in low half)
__device__ __forceinline__ void split2(float x, float y, unsigned &hi, unsigned &lo) {
    __nv_bfloat162 h = __floats2bfloat162_rn(x, y);
    float rx = x - __bfloat162float(__low2bfloat16(h));
    float ry = y - __bfloat162float(__high2bfloat16(h));
    __nv_bfloat162 l2 = __floats2bfloat162_rn(rx, ry);
    hi = *reinterpret_cast<unsigned*>(&h);
    lo = *reinterpret_cast<unsigned*>(&l2);
}
__device__ __forceinline__ float2 bf2f2(unsigned p) {
    __nv_bfloat162 b = *reinterpret_cast<__nv_bfloat162*>(&p);
    return __bfloat1622float2(b);
}

// m16n8k16 bf16 mma, D(f32) += A(bf16) * B(bf16)
__device__ __forceinline__ void mma_bf16(float (&d)[4], const unsigned (&a)[4],
                                         unsigned b0, unsigned b1) {
    asm volatile(
        "mma.sync.aligned.m16n8k16.row.col.f32.bf16.bf16.f32 "
        "{%0,%1,%2,%3}, {%4,%5,%6,%7}, {%8,%9}, {%0,%1,%2,%3};"
        : "+f"(d[0]), "+f"(d[1]), "+f"(d[2]), "+f"(d[3])
        : "r"(a[0]), "r"(a[1]), "r"(a[2]), "r"(a[3]), "r"(b0), "r"(b1));
}

// ---------------------------------------------------------------------------
// prep: repack in_proj / out_proj / x_proj into mma B-fragment order, hi/lo
// B frag (col-major 16x8): lane l -> n = l/4, k0 = (l%4)*2; reg0=(k0,k0+1), reg1=(k0+8,k0+9)
// ---------------------------------------------------------------------------
extern "C" __global__ void prep_kernel(const float* __restrict__ in_proj_w,
                                       const float* __restrict__ out_proj_w,
                                       const float* __restrict__ x_proj_w)
{
    int gid = blockIdx.x * blockDim.x + threadIdx.x;
    if (gid < NG1) {
        int lane = gid & 31; int rest = gid >> 5;
        int nt = rest % NT1; rest /= NT1;
        int kt = rest % KT1; int l = rest / KT1;
        int n  = nt * 8 + (lane >> 2);
        int k0 = kt * 16 + (lane & 3) * 2;
        const float* W = in_proj_w + (size_t)l * DMODEL * 1024;
        float v0 = W[(size_t)(k0    ) * 1024 + n];
        float v1 = W[(size_t)(k0 + 1) * 1024 + n];
        float v2 = W[(size_t)(k0 + 8) * 1024 + n];
        float v3 = W[(size_t)(k0 + 9) * 1024 + n];
        unsigned h0, l0, h1, l1;
        split2(v0, v1, h0, l0);
        split2(v2, v3, h1, l1);
        g_Whi1[gid] = make_uint2(h0, h1);
        g_Wlo1[gid] = make_uint2(l0, l1);
    } else if (gid < NG1 + NG3) {
        int g = gid - NG1;
        int lane = g & 31; int rest = g >> 5;
        int nt = rest % NT3; rest /= NT3;
        int kt = rest % KT3; int l = rest / KT3;
        int n  = nt * 8 + (lane >> 2);
        int k0 = kt * 16 + (lane & 3) * 2;
        const float* W = out_proj_w + (size_t)l * DINNER * DMODEL;
        float v0 = W[(size_t)(k0    ) * DMODEL + n];
        float v1 = W[(size_t)(k0 + 1) * DMODEL + n];
        float v2 = W[(size_t)(k0 + 8) * DMODEL + n];
        float v3 = W[(size_t)(k0 + 9) * DMODEL + n];
        unsigned h0, l0, h1, l1;
        split2(v0, v1, h0, l0);
        split2(v2, v3, h1, l1);
        g_Whi3[g] = make_uint2(h0, h1);
        g_Wlo3[g] = make_uint2(l0, l1);
    } else if (gid < NG1 + NG3 + NG2) {
        int g = gid - NG1 - NG3;
        int lane = g & 31; int rest = g >> 5;
        int nt = rest % NT2; rest /= NT2;
        int kt = rest % KT2; int l = rest / KT2;
        int n  = nt * 8 + (lane >> 2);
        int k0 = kt * 16 + (lane & 3) * 2;
        const float* W = x_proj_w + (size_t)l * DINNER * 48;
        float v0 = W[(size_t)(k0    ) * 48 + n];
        float v1 = W[(size_t)(k0 + 1) * 48 + n];
        float v2 = W[(size_t)(k0 + 8) * 48 + n];
        float v3 = W[(size_t)(k0 + 9) * 48 + n];
        unsigned h0, l0, h1, l1;
        split2(v0, v1, h0, l0);
        split2(v2, v3, h1, l1);
        g_Whi2[g] = make_uint2(h0, h1);
        g_Wlo2[g] = make_uint2(l0, l1);
    }
}

// ---------------------------------------------------------------------------
// main: one block = 16 batch rows, 2 CTAs/SM; all GEMMs via mma.
// Activations live in SMEM as bf16 hi/lo A-fragment arrays:
//   element (row r, col pair c,c+1): kt=c/16, lane=(r%8)*4+(c%8)/2,
//   reg=(r/8)+2*((c%16)/8)   (regs 0..3 contiguous per (kt,lane), LDS.128-able)
// SMEM: sh_h fp32 16x256 | sh_z fp32 16x512 | dbl | bc |
//       hfrag hi/lo (16kt) | xyfrag hi/lo (32kt, reused xc->y)   (~99 KB)
// ---------------------------------------------------------------------------
extern "C" __global__ void __launch_bounds__(NTHREADS, 2)
mamba_icl_kernel(const float* __restrict__ x,
                 const float* __restrict__ Wi,
                 const float* __restrict__ bi,
                 const float* __restrict__ conv_w,
                 const float* __restrict__ conv_b,
                 const float* __restrict__ dt_proj_w,
                 const float* __restrict__ dt_proj_b,
                 const float* __restrict__ Dvec,
                 const float* __restrict__ Wo,
                 const float* __restrict__ bo,
                 float* __restrict__ out)
{
    extern __shared__ float sm[];
    float*    sh_h      = sm;                    // 4096
    float*    sh_z      = sm + 4096;             // 8192
    float*    sh_dbl    = sm + 12288;            // 768
    float*    sh_bc     = sm + 13056;            // 16
    unsigned* hfrag_hi  = (unsigned*)(sm + 13072);      // 16*32*4 = 2048
    unsigned* hfrag_lo  = hfrag_hi + 2048;
    unsigned* xyfrag_hi = hfrag_lo + 2048;              // 32*32*4 = 4096
    unsigned* xyfrag_lo = xyfrag_hi + 4096;

    const int t    = threadIdx.x;
    const int row0 = blockIdx.x * ROWS;
    const int tx   = t & 127;
    const int ty   = t >> 7;
    const int wid  = t >> 5;
    const int lane = t & 31;
    const int fr   = lane >> 2;
    const int fc   = (lane & 3) * 2;

    // ---- stage x into sh_z scratch ----
    float* sh_x = sh_z;
    for (int idx = t; idx < ROWS * INDIM; idx += NTHREADS) {
        int r = idx / INDIM, c = idx - r * INDIM;
        sh_x[r * INDIM + c] = x[(size_t)(row0 + r) * INDIM + c];
    }
    __syncthreads();

    // ---- input projection (fp32 FFMA2, one-time) -> h-frags ----
    {
        F2 acc[8];
        #pragma unroll
        for (int i = 0; i < 8; i++) acc[i].f = make_float2(0.f, 0.f);
        const int rbase = ty * 8;
        #pragma unroll 2
        for (int k0 = 0; k0 < INDIM; k0 += 2) {
            F2 w0; w0.f = *(const float2*)(Wi + (size_t)k0 * DMODEL + tx * 2);
            F2 w1; w1.f = *(const float2*)(Wi + (size_t)(k0 + 1) * DMODEL + tx * 2);
            #pragma unroll
            for (int i = 0; i < 8; i++) {
                float2 a2 = *(const float2*)(sh_x + (rbase + i) * INDIM + k0);
                ffma2(acc[i], bcast2(a2.x), w0);
                ffma2(acc[i], bcast2(a2.y), w1);
            }
        }
        __syncthreads();   // done with sh_x before sh_z gets written (layer 0)
        float2 bv = *(const float2*)(bi + tx * 2);
        const int kt  = tx >> 3;
        const int reg = ty + 2 * ((tx >> 2) & 1);
        #pragma unroll
        for (int i = 0; i < 8; i++) {
            unsigned hh, ll;
            split2(acc[i].f.x + bv.x, acc[i].f.y + bv.y, hh, ll);
            int idx = (kt * 32 + i * 4 + (tx & 3)) * 4 + reg;
            hfrag_hi[idx] = hh;
            hfrag_lo[idx] = ll;
        }
    }
    __syncthreads();

    for (int l = 0; l < NLAYERS; l++) {
        const float* Cw = conv_w    + (size_t)l * DINNER * 4;
        const float* Cb = conv_b    + (size_t)l * DINNER;
        const float* Dw = dt_proj_w + (size_t)l * DTRANK * DINNER;
        const float* Db = dt_proj_b + (size_t)l * DINNER;
        const float* Dd = Dvec      + (size_t)l * DINNER;

        // ================= GEMM1: [16,256]@[256,1024] via mma ==============
        {
            float acc[16][4];
            #pragma unroll
            for (int nt = 0; nt < 16; nt++)
                #pragma unroll
                for (int j = 0; j < 4; j++) acc[nt][j] = 0.f;

            for (int kt = 0; kt < KT1; kt++) {
                unsigned ahi[4], alo[4];
                *(uint4*)ahi = *(const uint4*)&hfrag_hi[(kt * 32 + lane) * 4];
                *(uint4*)alo = *(const uint4*)&hfrag_lo[(kt * 32 + lane) * 4];

                const uint2* bh = g_Whi1 + (((size_t)l * KT1 + kt) * NT1 + wid * 16) * 32 + lane;
                const uint2* bl = g_Wlo1 + (((size_t)l * KT1 + kt) * NT1 + wid * 16) * 32 + lane;
                #pragma unroll
                for (int nt = 0; nt < 16; nt++) {
                    uint2 Bh = bh[nt * 32];
                    uint2 Bl = bl[nt * 32];
                    mma_bf16(acc[nt], ahi, Bh.x, Bh.y);
                    mma_bf16(acc[nt], alo, Bh.x, Bh.y);
                    mma_bf16(acc[nt], ahi, Bl.x, Bl.y);
                }
            }
            // epilogue
            if (wid < 4) {
                // xc = silu(conv tap3 * v + bias) -> xyfrag (bf16 split)
                #pragma unroll
                for (int nt = 0; nt < 16; nt++) {
                    int c = wid * 128 + nt * 8 + fc;
                    float cw0 = Cw[c * 4 + 3],       cb0 = Cb[c];
                    float cw1 = Cw[(c + 1) * 4 + 3], cb1 = Cb[c + 1];
                    float v00 = silu_f(acc[nt][0] * cw0 + cb0);
                    float v01 = silu_f(acc[nt][1] * cw1 + cb1);
                    float v10 = silu_f(acc[nt][2] * cw0 + cb0);
                    float v11 = silu_f(acc[nt][3] * cw1 + cb1);
                    unsigned h0, l0, h1, l1;
                    split2(v00, v01, h0, l0);
                    split2(v10, v11, h1, l1);
                    int idx = ((c >> 4) * 32 + lane) * 4 + 2 * (nt & 1);
                    *(uint2*)&xyfrag_hi[idx] = make_uint2(h0, h1);
                    *(uint2*)&xyfrag_lo[idx] = make_uint2(l0, l1);
                }
            } else {
                // silu(z) -> sh_z fp32
                #pragma unroll
                for (int nt = 0; nt < 16; nt++) {
                    int c = wid * 128 + nt * 8 + fc - 512;
                    *(float2*)&sh_z[fr * 512 + c] =
                        make_float2(silu_f(acc[nt][0]), silu_f(acc[nt][1]));
                    *(float2*)&sh_z[(fr + 8) * 512 + c] =
                        make_float2(silu_f(acc[nt][2]), silu_f(acc[nt][3]));
                }
            }
        }
        __syncthreads();

        // ================= GEMM2: dbl = xc @ x_proj [16,512]@[512,48] ======
        if (wid < NT2) {
            float d[4] = {0.f, 0.f, 0.f, 0.f};
            for (int kt = 0; kt < KT2; kt++) {
                unsigned ahi[4], alo[4];
                *(uint4*)ahi = *(const uint4*)&xyfrag_hi[(kt * 32 + lane) * 4];
                *(uint4*)alo = *(const uint4*)&xyfrag_lo[(kt * 32 + lane) * 4];
                uint2 Bh = g_Whi2[(((size_t)l * KT2 + kt) * NT2 + wid) * 32 + lane];
                uint2 Bl = g_Wlo2[(((size_t)l * KT2 + kt) * NT2 + wid) * 32 + lane];
                mma_bf16(d, ahi, Bh.x, Bh.y);
                mma_bf16(d, alo, Bh.x, Bh.y);
                mma_bf16(d, ahi, Bl.x, Bl.y);
            }
            int c = wid * 8 + fc;
            *(float2*)&sh_dbl[fr * 48 + c]       = make_float2(d[0], d[1]);
            *(float2*)&sh_dbl[(fr + 8) * 48 + c] = make_float2(d[2], d[3]);
        }
        __syncthreads();

        // ---- bc[r] = dot(B, C) ----
        if (t < ROWS) {
            float s = 0.f;
            #pragma unroll
            for (int j = 0; j < DSTATE; j++)
                s = fmaf(sh_dbl[t * 48 + DTRANK + j], sh_dbl[t * 48 + DTRANK + DSTATE + j], s);
            sh_bc[t] = s;
        }
        __syncthreads();

        // ---- gating: y = xc * (softplus(dt)*bc + D) * silu(z), in-place frag
        {
            const int c    = t * 2;
            const int ktg  = t >> 3;
            const int rb   = 2 * ((t >> 2) & 1);
            F2 dw[DTRANK];
            #pragma unroll
            for (int j = 0; j < DTRANK; j++)
                dw[j].f = *(const float2*)(Dw + j * DINNER + c);
            const float2 dbv = *(const float2*)(Db + c);
            const float2 ddv = *(const float2*)(Dd + c);

            #pragma unroll 2
            for (int r = 0; r < ROWS; r++) {
                float4 d0 = *(const float4*)(sh_dbl + r * 48);
                float4 d1 = *(const float4*)(sh_dbl + r * 48 + 4);
                float4 d2 = *(const float4*)(sh_dbl + r * 48 + 8);
                float4 d3 = *(const float4*)(sh_dbl + r * 48 + 12);
                F2 sdt; sdt.f = dbv;
                ffma2(sdt, bcast2(d0.x), dw[0]);  ffma2(sdt, bcast2(d0.y), dw[1]);
                ffma2(sdt, bcast2(d0.z), dw[2]);  ffma2(sdt, bcast2(d0.w), dw[3]);
                ffma2(sdt, bcast2(d1.x), dw[4]);  ffma2(sdt, bcast2(d1.y), dw[5]);
                ffma2(sdt, bcast2(d1.z), dw[6]);  ffma2(sdt, bcast2(d1.w), dw[7]);
                ffma2(sdt, bcast2(d2.x), dw[8]);  ffma2(sdt, bcast2(d2.y), dw[9]);
                ffma2(sdt, bcast2(d2.z), dw[10]); ffma2(sdt, bcast2(d2.w), dw[11]);
                ffma2(sdt, bcast2(d3.x), dw[12]); ffma2(sdt, bcast2(d3.y), dw[13]);
                ffma2(sdt, bcast2(d3.z), dw[14]); ffma2(sdt, bcast2(d3.w), dw[15]);
                float dt0 = softplus_f(sdt.f.x);
                float dt1 = softplus_f(sdt.f.y);
                float bcr = sh_bc[r];

                int idx = (ktg * 32 + (r & 7) * 4 + (t & 3)) * 4 + rb + (r >> 3);
                float2 xh = bf2f2(xyfrag_hi[idx]);
                float2 xl = bf2f2(xyfrag_lo[idx]);
                float xc0 = xh.x + xl.x;
                float xc1 = xh.y + xl.y;
                float2 sz = *(const float2*)&sh_z[r * 512 + c];
                float y0 = xc0 * (dt0 * bcr + ddv.x) * sz.x;
                float y1 = xc1 * (dt1 * bcr + ddv.y) * sz.y;
                unsigned nh, nl;
                split2(y0, y1, nh, nl);
                xyfrag_hi[idx] = nh;
                xyfrag_lo[idx] = nl;
            }
        }
        __syncthreads();

        // ================= GEMM3: h = y @ out_proj [16,512]@[512,256] ======
        {
            float acc3[4][4];
            #pragma unroll
            for (int nt = 0; nt < 4; nt++)
                #pragma unroll
                for (int j = 0; j < 4; j++) acc3[nt][j] = 0.f;

            for (int kt = 0; kt < KT3; kt++) {
                unsigned ahi[4], alo[4];
                *(uint4*)ahi = *(const uint4*)&xyfrag_hi[(kt * 32 + lane) * 4];
                *(uint4*)alo = *(const uint4*)&xyfrag_lo[(kt * 32 + lane) * 4];
                const uint2* bh = g_Whi3 + (((size_t)l * KT3 + kt) * NT3 + wid * 4) * 32 + lane;
                const uint2* bl = g_Wlo3 + (((size_t)l * KT3 + kt) * NT3 + wid * 4) * 32 + lane;
                #pragma unroll
                for (int nt = 0; nt < 4; nt++) {
                    uint2 Bh = bh[nt * 32];
                    uint2 Bl = bl[nt * 32];
                    mma_bf16(acc3[nt], ahi, Bh.x, Bh.y);
                    mma_bf16(acc3[nt], alo, Bh.x, Bh.y);
                    mma_bf16(acc3[nt], ahi, Bl.x, Bl.y);
                }
            }
            // epilogue: h-frags (next GEMM1) + fp32 h (head)
            #pragma unroll
            for (int nt = 0; nt < 4; nt++) {
                int c = wid * 32 + nt * 8 + fc;
                unsigned h0, l0, h1, l1;
                split2(acc3[nt][0], acc3[nt][1], h0, l0);
                split2(acc3[nt][2], acc3[nt][3], h1, l1);
                int idx = ((c >> 4) * 32 + lane) * 4 + 2 * (nt & 1);
                *(uint2*)&hfrag_hi[idx] = make_uint2(h0, h1);
                *(uint2*)&hfrag_lo[idx] = make_uint2(l0, l1);
                *(float2*)&sh_h[fr * DMODEL + c]       = make_float2(acc3[nt][0], acc3[nt][1]);
                *(float2*)&sh_h[(fr + 8) * DMODEL + c] = make_float2(acc3[nt][2], acc3[nt][3]);
            }
        }
        __syncthreads();
    }

    // ---- output head ----
    if (t < ROWS) {
        float s = 0.f;
        #pragma unroll 8
        for (int m = 0; m < DMODEL; m++)
            s = fmaf(sh_h[t * DMODEL + m], Wo[m], s);
        out[row0 + t] = s + bo[0];
    }
}

// ---------------------------------------------------------------------------
extern "C" void kernel_launch(void* const* d_in, const int* in_sizes, int n_in,
                              void* d_out, int out_size)
{
    (void)in_sizes; (void)n_in; (void)out_size;

    prep_kernel<<<(NG1 + NG3 + NG2 + 255) / 256, 256>>>(
        (const float*)d_in[3],    // in_proj_w
        (const float*)d_in[11],   // out_proj_w
        (const float*)d_in[6]);   // x_proj_w

    const size_t smem_bytes = (size_t)(13072 + 2048 * 2 + 4096 * 2) * 4;  // 101440

    cudaFuncSetAttribute(mamba_icl_kernel,
                         cudaFuncAttributeMaxDynamicSharedMemorySize,
                         (int)smem_bytes);

    mamba_icl_kernel<<<BATCH / ROWS, NTHREADS, smem_bytes>>>(
        (const float*)d_in[0],   // x
        (const float*)d_in[1],   // Wi
        (const float*)d_in[2],   // bi
        (const float*)d_in[4],   // conv_w
        (const float*)d_in[5],   // conv_b
        (const float*)d_in[7],   // dt_proj_w
        (const float*)d_in[8],   // dt_proj_b
        // d_in[9] = A_log dead (h0 = 0, L = 1)
        (const float*)d_in[10],  // D
        (const float*)d_in[12],  // Wo
        (const float*)d_in[13],  // bo
        (float*)d_out);
}